// round 2
// baseline (speedup 1.0000x reference)
#include <cuda_runtime.h>
#include <cuda_bf16.h>
#include <cstdint>

#define NN 100000          // nodes
#define CC 128             // channels

// ---------------- scratch (static device globals; no allocs allowed) -------
__device__ __align__(16) float  g_agg[(size_t)NN * CC];   // 51.2 MB
__device__ __align__(16) float  g_h[(size_t)NN * CC];     // 51.2 MB
__device__ double g_sum[CC];
__device__ double g_sumsq[CC];
__device__ __align__(16) float g_scale[CC];
__device__ __align__(16) float g_shift[CC];

// ---------------- zero agg + stats ----------------
__global__ void __launch_bounds__(256) k_zero()
{
    size_t i = (size_t)blockIdx.x * 256 + threadIdx.x;
    if (i < (size_t)NN * (CC / 4))
        ((float4*)g_agg)[i] = make_float4(0.f, 0.f, 0.f, 0.f);
    if (blockIdx.x == 0 && threadIdx.x < CC) {
        g_sum[threadIdx.x] = 0.0;
        g_sumsq[threadIdx.x] = 0.0;
    }
}

// ---------------- scatter-add: warp per edge, lane handles 4 channels ------
// AFF=1: source is g_h with fused BN affine + ReLU applied on the fly.
template<int AFF>
__global__ void __launch_bounds__(256) k_scatter(const float* __restrict__ xin,
                                                 const int* __restrict__ src,
                                                 const int* __restrict__ dst,
                                                 const float* __restrict__ ew,
                                                 int E)
{
    int gw   = (int)(((unsigned)blockIdx.x * 256u + threadIdx.x) >> 5);
    int lane = threadIdx.x & 31;
    if (gw >= E) return;

    int   s = __ldg(src + gw);
    int   d = __ldg(dst + gw);
    float w = __ldg(ew + gw);

    const float* x = AFF ? (const float*)g_h : xin;
    float4 v = *(const float4*)(x + (size_t)s * CC + lane * 4);

    if (AFF) {
        float4 sc = *(const float4*)(g_scale + lane * 4);
        float4 sh = *(const float4*)(g_shift + lane * 4);
        v.x = fmaxf(fmaf(v.x, sc.x, sh.x), 0.f);
        v.y = fmaxf(fmaf(v.y, sc.y, sh.y), 0.f);
        v.z = fmaxf(fmaf(v.z, sc.z, sh.z), 0.f);
        v.w = fmaxf(fmaf(v.w, sc.w, sh.w), 0.f);
    }
    v.x *= w; v.y *= w; v.z *= w; v.w *= w;

    float* p = g_agg + (size_t)d * CC + lane * 4;
    asm volatile("red.global.add.v4.f32 [%0], {%1,%2,%3,%4};"
                 :: "l"(p), "f"(v.x), "f"(v.y), "f"(v.z), "f"(v.w) : "memory");
}

// ---------------- 128x128 GEMM (h = agg @ W) with fused BN stats -----------
// Block: 256 threads (16x16), tile 128 rows x 128 cols, thread tile 8x8.
// Uses packed fma.rn.f32x2 (full-rate fp32 on sm_103a; plain FFMA is rt=2).
#define SMEM_GEMM_FLOATS (16384 + 128 * 132 + 256)
__global__ void __launch_bounds__(256) k_gemm128(const float* __restrict__ Wg,
                                                 int doStats)
{
    extern __shared__ float sm[];
    float* Ws   = sm;               // 128*128
    float* As   = sm + 16384;       // 128 rows * 132 (padded) floats
    float* csum = As + 128 * 132;   // 128
    float* csq  = csum + 128;       // 128

    const int tid = threadIdx.x;
    const int tx  = tid & 15;
    const int ty  = tid >> 4;
    const int rowBase = blockIdx.x * 128;

    {   // load W (row-major [k][c]) into smem
        const float4* W4  = (const float4*)Wg;
        float4*       Ws4 = (float4*)Ws;
        #pragma unroll
        for (int i = 0; i < 16; i++) Ws4[i * 256 + tid] = W4[i * 256 + tid];
    }
    #pragma unroll
    for (int i = 0; i < 16; i++) {   // load A tile, padded stride 132
        int fl  = i * 256 + tid;     // float4 index within tile
        int row = fl >> 5;
        int k4  = fl & 31;
        int grow = rowBase + row;
        float4 v = make_float4(0.f, 0.f, 0.f, 0.f);
        if (grow < NN) v = ((const float4*)g_agg)[(size_t)grow * 32 + k4];
        *(float4*)(As + row * 132 + k4 * 4) = v;
    }
    if (tid < 128) { csum[tid] = 0.f; csq[tid] = 0.f; }
    __syncthreads();

    unsigned long long acc[8][4];
    #pragma unroll
    for (int r = 0; r < 8; r++)
        #pragma unroll
        for (int c = 0; c < 4; c++) acc[r][c] = 0ull;

    const int    colBase = tx * 8;
    const float* AsR     = As + (ty * 8) * 132;

    #pragma unroll 4
    for (int k = 0; k < 128; k++) {
        const ulonglong2* wp = (const ulonglong2*)(Ws + k * 128 + colBase);
        ulonglong2 p0 = wp[0];
        ulonglong2 p1 = wp[1];
        unsigned long long bb0 = p0.x, bb1 = p0.y, bb2 = p1.x, bb3 = p1.y;
        #pragma unroll
        for (int r = 0; r < 8; r++) {
            float a = AsR[r * 132 + k];
            unsigned long long aa;
            asm("mov.b64 %0, {%1, %1};" : "=l"(aa) : "f"(a));
            asm("fma.rn.f32x2 %0, %1, %2, %0;" : "+l"(acc[r][0]) : "l"(aa), "l"(bb0));
            asm("fma.rn.f32x2 %0, %1, %2, %0;" : "+l"(acc[r][1]) : "l"(aa), "l"(bb1));
            asm("fma.rn.f32x2 %0, %1, %2, %0;" : "+l"(acc[r][2]) : "l"(aa), "l"(bb2));
            asm("fma.rn.f32x2 %0, %1, %2, %0;" : "+l"(acc[r][3]) : "l"(aa), "l"(bb3));
        }
    }

    // epilogue: store h + per-thread BN partials
    float psum[8], psq[8];
    #pragma unroll
    for (int j = 0; j < 8; j++) { psum[j] = 0.f; psq[j] = 0.f; }

    #pragma unroll
    for (int r = 0; r < 8; r++) {
        int grow = rowBase + ty * 8 + r;
        float v[8];
        #pragma unroll
        for (int c = 0; c < 4; c++)
            asm("mov.b64 {%0, %1}, %2;"
                : "=f"(v[c * 2]), "=f"(v[c * 2 + 1]) : "l"(acc[r][c]));
        if (grow < NN) {
            *(float4*)(g_h + (size_t)grow * CC + colBase)     = make_float4(v[0], v[1], v[2], v[3]);
            *(float4*)(g_h + (size_t)grow * CC + colBase + 4) = make_float4(v[4], v[5], v[6], v[7]);
            #pragma unroll
            for (int j = 0; j < 8; j++) { psum[j] += v[j]; psq[j] += v[j] * v[j]; }
        }
    }
    if (doStats) {
        #pragma unroll
        for (int j = 0; j < 8; j++) {
            atomicAdd(&csum[colBase + j], psum[j]);
            atomicAdd(&csq[colBase + j],  psq[j]);
        }
        __syncthreads();
        if (tid < 128) {
            atomicAdd(&g_sum[tid],   (double)csum[tid]);
            atomicAdd(&g_sumsq[tid], (double)csq[tid]);
        }
    }
}

// ---------------- BN coefficients: scale/shift from sums -------------------
__global__ void k_finalize(const float* __restrict__ gamma,
                           const float* __restrict__ beta)
{
    int c = threadIdx.x;
    double mean = g_sum[c] / (double)NN;
    double var  = g_sumsq[c] / (double)NN - mean * mean;
    float sc = gamma[c] * rsqrtf((float)var + 1e-5f);
    g_scale[c] = sc;
    g_shift[c] = beta[c] - (float)mean * sc;
}

// ---------------- final GEMM 128 -> 40 with bias, writes d_out -------------
#define SMEM_OUT_FLOATS (5120 + 128 * 132)
__global__ void __launch_bounds__(256) k_gemm_out(const float* __restrict__ W3,
                                                  const float* __restrict__ b3,
                                                  float* __restrict__ out)
{
    extern __shared__ float sm[];
    float* Ws = sm;            // 128*40
    float* As = sm + 5120;     // 128*132

    const int tid = threadIdx.x;
    const int rowBase = blockIdx.x * 128;

    for (int i = tid; i < 5120; i += 256) Ws[i] = W3[i];
    #pragma unroll
    for (int i = 0; i < 16; i++) {
        int fl  = i * 256 + tid;
        int row = fl >> 5;
        int k4  = fl & 31;
        int grow = rowBase + row;
        float4 v = make_float4(0.f, 0.f, 0.f, 0.f);
        if (grow < NN) v = ((const float4*)g_agg)[(size_t)grow * 32 + k4];
        *(float4*)(As + row * 132 + k4 * 4) = v;
    }
    __syncthreads();

    const int cg = tid & 7;    // 8 col groups x 5 cols
    const int rg = tid >> 3;   // 32 row groups x 4 rows
    float acc[4][5];
    #pragma unroll
    for (int r = 0; r < 4; r++)
        #pragma unroll
        for (int j = 0; j < 5; j++) acc[r][j] = 0.f;

    #pragma unroll 2
    for (int k = 0; k < 128; k++) {
        float b[5];
        #pragma unroll
        for (int j = 0; j < 5; j++) b[j] = Ws[k * 40 + cg * 5 + j];
        #pragma unroll
        for (int r = 0; r < 4; r++) {
            float a = As[(rg * 4 + r) * 132 + k];
            #pragma unroll
            for (int j = 0; j < 5; j++) acc[r][j] = fmaf(a, b[j], acc[r][j]);
        }
    }
    #pragma unroll
    for (int r = 0; r < 4; r++) {
        int grow = rowBase + rg * 4 + r;
        if (grow < NN) {
            #pragma unroll
            for (int j = 0; j < 5; j++)
                out[(size_t)grow * 40 + cg * 5 + j] = acc[r][j] + b3[cg * 5 + j];
        }
    }
}

// ---------------- launch ---------------------------------------------------
extern "C" void kernel_launch(void* const* d_in, const int* in_sizes, int n_in,
                              void* d_out, int out_size)
{
    const float* feat   = (const float*)d_in[0];
    const int*   src    = (const int*)  d_in[1];
    const int*   dst    = (const int*)  d_in[2];
    const float* ew     = (const float*)d_in[3];
    const float* W1     = (const float*)d_in[4];
    const float* W2     = (const float*)d_in[5];
    const float* W3     = (const float*)d_in[6];
    const float* b3     = (const float*)d_in[7];
    const float* gamma1 = (const float*)d_in[8];
    const float* beta1  = (const float*)d_in[9];
    const float* gamma2 = (const float*)d_in[10];
    const float* beta2  = (const float*)d_in[11];
    float* out = (float*)d_out;
    const int E = in_sizes[1];

    const int smemGemm = SMEM_GEMM_FLOATS * 4;   // 134144 B
    const int smemOut  = SMEM_OUT_FLOATS  * 4;   //  88064 B
    cudaFuncSetAttribute(k_gemm128, cudaFuncAttributeMaxDynamicSharedMemorySize, smemGemm);
    cudaFuncSetAttribute(k_gemm_out, cudaFuncAttributeMaxDynamicSharedMemorySize, smemOut);

    const int zgrid = (NN * (CC / 4) + 255) / 256;
    const int sgrid = (int)(((long long)E * 32 + 255) / 256);
    const int ggrid = (NN + 127) / 128;

    // ---- layer 1 ----
    k_zero<<<zgrid, 256>>>();
    k_scatter<0><<<sgrid, 256>>>(feat, src, dst, ew, E);
    k_gemm128<<<ggrid, 256, smemGemm>>>(W1, 1);
    k_finalize<<<1, 128>>>(gamma1, beta1);

    // ---- layer 2 (BN+ReLU of layer1 fused into the gather) ----
    k_zero<<<zgrid, 256>>>();
    k_scatter<1><<<sgrid, 256>>>(nullptr, src, dst, ew, E);
    k_gemm128<<<ggrid, 256, smemGemm>>>(W2, 1);
    k_finalize<<<1, 128>>>(gamma2, beta2);

    // ---- layer 3 ----
    k_zero<<<zgrid, 256>>>();
    k_scatter<1><<<sgrid, 256>>>(nullptr, src, dst, ew, E);
    k_gemm_out<<<ggrid, 256, smemOut>>>(W3, b3, out);
}

// round 5
// speedup vs baseline: 1.7003x; 1.7003x over previous
#include <cuda_runtime.h>
#include <cuda_bf16.h>
#include <cstdint>

#define NN   100000
#define CC   128
#define EMAX 1600000
#define NB   ((NN + 255) / 256)        // 391 scan blocks

// ---------------- scratch (static device globals) --------------------------
__device__ __align__(16) float g_agg[(size_t)NN * CC];   // 51.2 MB
__device__ __align__(16) float g_h[(size_t)NN * CC];     // 51.2 MB
__device__ int   g_cnt[NN];
__device__ int   g_rowstart[NN];
__device__ int   g_cursor[NN];
__device__ int   g_bsum[NB];
__device__ int   g_boff[NB];
__device__ int   g_psrc[EMAX];
__device__ float g_pw[EMAX];
__device__ double g_sum[2][CC];
__device__ double g_sumsq[2][CC];

// ---------------- CSR build ------------------------------------------------
__global__ void __launch_bounds__(256) k_init()
{
    int i = blockIdx.x * 256 + threadIdx.x;
    if (i < NN) g_cnt[i] = 0;
    if (blockIdx.x == 0 && threadIdx.x < CC) {
        g_sum[0][threadIdx.x] = 0.0;  g_sumsq[0][threadIdx.x] = 0.0;
        g_sum[1][threadIdx.x] = 0.0;  g_sumsq[1][threadIdx.x] = 0.0;
    }
}

__global__ void __launch_bounds__(256) k_hist(const int* __restrict__ dst, int E)
{
    int e = blockIdx.x * 256 + threadIdx.x;
    if (e < E) atomicAdd(&g_cnt[dst[e]], 1);
}

__global__ void __launch_bounds__(256) k_scan1()
{
    __shared__ int sm[256];
    int tid = threadIdx.x;
    int i = blockIdx.x * 256 + tid;
    int c = (i < NN) ? g_cnt[i] : 0;
    sm[tid] = c;
    __syncthreads();
    #pragma unroll
    for (int off = 1; off < 256; off <<= 1) {
        int v = (tid >= off) ? sm[tid - off] : 0;
        __syncthreads();
        sm[tid] += v;
        __syncthreads();
    }
    if (i < NN) g_rowstart[i] = sm[tid] - c;       // local exclusive
    if (tid == 255) g_bsum[blockIdx.x] = sm[255];  // block total
}

__global__ void __launch_bounds__(512) k_scan2()
{
    __shared__ int sm[512];
    int tid = threadIdx.x;
    int v = (tid < NB) ? g_bsum[tid] : 0;
    sm[tid] = v;
    __syncthreads();
    #pragma unroll
    for (int off = 1; off < 512; off <<= 1) {
        int u = (tid >= off) ? sm[tid - off] : 0;
        __syncthreads();
        sm[tid] += u;
        __syncthreads();
    }
    if (tid < NB) g_boff[tid] = sm[tid] - v;       // exclusive
}

__global__ void __launch_bounds__(256) k_scan3()
{
    int i = blockIdx.x * 256 + threadIdx.x;
    if (i < NN) {
        int r = g_rowstart[i] + g_boff[blockIdx.x];
        g_rowstart[i] = r;
        g_cursor[i]   = r;
    }
}

__global__ void __launch_bounds__(256) k_fill(const int* __restrict__ src,
                                              const int* __restrict__ dst,
                                              const float* __restrict__ ew,
                                              int E)
{
    int e = blockIdx.x * 256 + threadIdx.x;
    if (e < E) {
        int slot = atomicAdd(&g_cursor[dst[e]], 1);
        g_psrc[slot] = src[e];
        g_pw[slot]   = ew[e];
    }
}

// ---------------- gather aggregation: warp per node ------------------------
// AFF=0: source rows come from the xin argument (harness device pointer).
// AFF=1: source rows come from the DEVICE SYMBOL g_h (bound in device code —
//        device symbols must NEVER be passed as kernel args from host), with
//        BN affine + ReLU applied on the fly from g_sum[sel]/g_sumsq[sel].
template<int AFF>
__global__ void __launch_bounds__(256) k_gather(const float* __restrict__ xin,
                                                int sel,
                                                const float* __restrict__ gamma,
                                                const float* __restrict__ beta)
{
    __shared__ float s_sc[CC], s_sh[CC];
    const int tid  = threadIdx.x;
    const int lane = tid & 31;

    const float* __restrict__ x = AFF ? (const float*)g_h : xin;

    if (AFF) {
        if (tid < CC) {
            double mean = g_sum[sel][tid]   * (1.0 / NN);
            double var  = g_sumsq[sel][tid] * (1.0 / NN) - mean * mean;
            float sc = gamma[tid] * rsqrtf((float)var + 1e-5f);
            s_sc[tid] = sc;
            s_sh[tid] = beta[tid] - (float)mean * sc;
        }
        __syncthreads();
    }

    int v = blockIdx.x * 8 + (tid >> 5);
    if (v >= NN) return;

    float4 sc4, sh4;
    if (AFF) {
        sc4 = *(const float4*)(s_sc + lane * 4);
        sh4 = *(const float4*)(s_sh + lane * 4);
    }

    const int start = g_rowstart[v];
    const int deg   = g_cnt[v];
    float4 acc = make_float4(0.f, 0.f, 0.f, 0.f);

    int j = 0;
    for (; j + 2 <= deg; j += 2) {
        int   s0 = g_psrc[start + j],     s1 = g_psrc[start + j + 1];
        float w0 = g_pw[start + j],       w1 = g_pw[start + j + 1];
        float4 x0 = *(const float4*)(x + (size_t)s0 * CC + lane * 4);
        float4 x1 = *(const float4*)(x + (size_t)s1 * CC + lane * 4);
        if (AFF) {
            x0.x = fmaxf(fmaf(x0.x, sc4.x, sh4.x), 0.f);
            x0.y = fmaxf(fmaf(x0.y, sc4.y, sh4.y), 0.f);
            x0.z = fmaxf(fmaf(x0.z, sc4.z, sh4.z), 0.f);
            x0.w = fmaxf(fmaf(x0.w, sc4.w, sh4.w), 0.f);
            x1.x = fmaxf(fmaf(x1.x, sc4.x, sh4.x), 0.f);
            x1.y = fmaxf(fmaf(x1.y, sc4.y, sh4.y), 0.f);
            x1.z = fmaxf(fmaf(x1.z, sc4.z, sh4.z), 0.f);
            x1.w = fmaxf(fmaf(x1.w, sc4.w, sh4.w), 0.f);
        }
        acc.x = fmaf(w0, x0.x, fmaf(w1, x1.x, acc.x));
        acc.y = fmaf(w0, x0.y, fmaf(w1, x1.y, acc.y));
        acc.z = fmaf(w0, x0.z, fmaf(w1, x1.z, acc.z));
        acc.w = fmaf(w0, x0.w, fmaf(w1, x1.w, acc.w));
    }
    if (j < deg) {
        int   s0 = g_psrc[start + j];
        float w0 = g_pw[start + j];
        float4 x0 = *(const float4*)(x + (size_t)s0 * CC + lane * 4);
        if (AFF) {
            x0.x = fmaxf(fmaf(x0.x, sc4.x, sh4.x), 0.f);
            x0.y = fmaxf(fmaf(x0.y, sc4.y, sh4.y), 0.f);
            x0.z = fmaxf(fmaf(x0.z, sc4.z, sh4.z), 0.f);
            x0.w = fmaxf(fmaf(x0.w, sc4.w, sh4.w), 0.f);
        }
        acc.x = fmaf(w0, x0.x, acc.x);
        acc.y = fmaf(w0, x0.y, acc.y);
        acc.z = fmaf(w0, x0.z, acc.z);
        acc.w = fmaf(w0, x0.w, acc.w);
    }
    *(float4*)(g_agg + (size_t)v * CC + lane * 4) = acc;
}

// ---------------- 128x128 GEMM (h = agg @ W) with fused BN stats -----------
#define SMEM_GEMM_FLOATS (16384 + 128 * 132 + 256)
__global__ void __launch_bounds__(256) k_gemm128(const float* __restrict__ Wg,
                                                 int sel)
{
    extern __shared__ float sm[];
    float* Ws   = sm;               // 128*128
    float* As   = sm + 16384;       // 128 * 132 (padded)
    float* csum = As + 128 * 132;   // 128
    float* csq  = csum + 128;       // 128

    const int tid = threadIdx.x;
    const int tx  = tid & 15;
    const int ty  = tid >> 4;
    const int rowBase = blockIdx.x * 128;

    {
        const float4* W4  = (const float4*)Wg;
        float4*       Ws4 = (float4*)Ws;
        #pragma unroll
        for (int i = 0; i < 16; i++) Ws4[i * 256 + tid] = W4[i * 256 + tid];
    }
    #pragma unroll
    for (int i = 0; i < 16; i++) {
        int fl  = i * 256 + tid;
        int row = fl >> 5;
        int k4  = fl & 31;
        int grow = rowBase + row;
        float4 v = make_float4(0.f, 0.f, 0.f, 0.f);
        if (grow < NN) v = ((const float4*)g_agg)[(size_t)grow * 32 + k4];
        *(float4*)(As + row * 132 + k4 * 4) = v;
    }
    if (tid < 128) { csum[tid] = 0.f; csq[tid] = 0.f; }
    __syncthreads();

    unsigned long long acc[8][4];
    #pragma unroll
    for (int r = 0; r < 8; r++)
        #pragma unroll
        for (int c = 0; c < 4; c++) acc[r][c] = 0ull;

    const int    colBase = tx * 8;
    const float* AsR     = As + (ty * 8) * 132;

    #pragma unroll 4
    for (int k = 0; k < 128; k++) {
        const ulonglong2* wp = (const ulonglong2*)(Ws + k * 128 + colBase);
        ulonglong2 p0 = wp[0];
        ulonglong2 p1 = wp[1];
        unsigned long long bb0 = p0.x, bb1 = p0.y, bb2 = p1.x, bb3 = p1.y;
        #pragma unroll
        for (int r = 0; r < 8; r++) {
            float a = AsR[r * 132 + k];
            unsigned long long aa;
            asm("mov.b64 %0, {%1, %1};" : "=l"(aa) : "f"(a));
            asm("fma.rn.f32x2 %0, %1, %2, %0;" : "+l"(acc[r][0]) : "l"(aa), "l"(bb0));
            asm("fma.rn.f32x2 %0, %1, %2, %0;" : "+l"(acc[r][1]) : "l"(aa), "l"(bb1));
            asm("fma.rn.f32x2 %0, %1, %2, %0;" : "+l"(acc[r][2]) : "l"(aa), "l"(bb2));
            asm("fma.rn.f32x2 %0, %1, %2, %0;" : "+l"(acc[r][3]) : "l"(aa), "l"(bb3));
        }
    }

    float psum[8], psq[8];
    #pragma unroll
    for (int jj = 0; jj < 8; jj++) { psum[jj] = 0.f; psq[jj] = 0.f; }

    #pragma unroll
    for (int r = 0; r < 8; r++) {
        int grow = rowBase + ty * 8 + r;
        float v[8];
        #pragma unroll
        for (int c = 0; c < 4; c++)
            asm("mov.b64 {%0, %1}, %2;"
                : "=f"(v[c * 2]), "=f"(v[c * 2 + 1]) : "l"(acc[r][c]));
        if (grow < NN) {
            *(float4*)(g_h + (size_t)grow * CC + colBase)     = make_float4(v[0], v[1], v[2], v[3]);
            *(float4*)(g_h + (size_t)grow * CC + colBase + 4) = make_float4(v[4], v[5], v[6], v[7]);
            #pragma unroll
            for (int jj = 0; jj < 8; jj++) { psum[jj] += v[jj]; psq[jj] += v[jj] * v[jj]; }
        }
    }
    #pragma unroll
    for (int jj = 0; jj < 8; jj++) {
        atomicAdd(&csum[colBase + jj], psum[jj]);
        atomicAdd(&csq[colBase + jj],  psq[jj]);
    }
    __syncthreads();
    if (tid < 128) {
        atomicAdd(&g_sum[sel][tid],   (double)csum[tid]);
        atomicAdd(&g_sumsq[sel][tid], (double)csq[tid]);
    }
}

// ---------------- final GEMM 128 -> 40 with bias, writes d_out -------------
#define SMEM_OUT_FLOATS (5120 + 128 * 132)
__global__ void __launch_bounds__(256) k_gemm_out(const float* __restrict__ W3,
                                                  const float* __restrict__ b3,
                                                  float* __restrict__ out)
{
    extern __shared__ float sm[];
    float* Ws = sm;            // 128*40
    float* As = sm + 5120;     // 128*132

    const int tid = threadIdx.x;
    const int rowBase = blockIdx.x * 128;

    for (int i = tid; i < 5120; i += 256) Ws[i] = W3[i];
    #pragma unroll
    for (int i = 0; i < 16; i++) {
        int fl  = i * 256 + tid;
        int row = fl >> 5;
        int k4  = fl & 31;
        int grow = rowBase + row;
        float4 v = make_float4(0.f, 0.f, 0.f, 0.f);
        if (grow < NN) v = ((const float4*)g_agg)[(size_t)grow * 32 + k4];
        *(float4*)(As + row * 132 + k4 * 4) = v;
    }
    __syncthreads();

    const int cg = tid & 7;
    const int rg = tid >> 3;
    float acc[4][5];
    #pragma unroll
    for (int r = 0; r < 4; r++)
        #pragma unroll
        for (int j = 0; j < 5; j++) acc[r][j] = 0.f;

    #pragma unroll 2
    for (int k = 0; k < 128; k++) {
        float b[5];
        #pragma unroll
        for (int j = 0; j < 5; j++) b[j] = Ws[k * 40 + cg * 5 + j];
        #pragma unroll
        for (int r = 0; r < 4; r++) {
            float a = As[(rg * 4 + r) * 132 + k];
            #pragma unroll
            for (int j = 0; j < 5; j++) acc[r][j] = fmaf(a, b[j], acc[r][j]);
        }
    }
    #pragma unroll
    for (int r = 0; r < 4; r++) {
        int grow = rowBase + rg * 4 + r;
        if (grow < NN) {
            #pragma unroll
            for (int j = 0; j < 5; j++)
                out[(size_t)grow * 40 + cg * 5 + j] = acc[r][j] + b3[cg * 5 + j];
        }
    }
}

// ---------------- launch ---------------------------------------------------
extern "C" void kernel_launch(void* const* d_in, const int* in_sizes, int n_in,
                              void* d_out, int out_size)
{
    const float* feat   = (const float*)d_in[0];
    const int*   src    = (const int*)  d_in[1];
    const int*   dst    = (const int*)  d_in[2];
    const float* ew     = (const float*)d_in[3];
    const float* W1     = (const float*)d_in[4];
    const float* W2     = (const float*)d_in[5];
    const float* W3     = (const float*)d_in[6];
    const float* b3     = (const float*)d_in[7];
    const float* gamma1 = (const float*)d_in[8];
    const float* beta1  = (const float*)d_in[9];
    const float* gamma2 = (const float*)d_in[10];
    const float* beta2  = (const float*)d_in[11];
    float* out = (float*)d_out;
    const int E = in_sizes[1];

    const int smemGemm = SMEM_GEMM_FLOATS * 4;
    const int smemOut  = SMEM_OUT_FLOATS  * 4;
    cudaFuncSetAttribute(k_gemm128,  cudaFuncAttributeMaxDynamicSharedMemorySize, smemGemm);
    cudaFuncSetAttribute(k_gemm_out, cudaFuncAttributeMaxDynamicSharedMemorySize, smemOut);

    const int egrid = (E + 255) / 256;
    const int ggrid = (NN + 127) / 128;
    const int agrid = (NN + 7) / 8;

    // ---- build CSR (shared by all 3 layers) ----
    k_init <<<NB, 256>>>();
    k_hist <<<egrid, 256>>>(dst, E);
    k_scan1<<<NB, 256>>>();
    k_scan2<<<1, 512>>>();
    k_scan3<<<NB, 256>>>();
    k_fill <<<egrid, 256>>>(src, dst, ew, E);

    // ---- layer 1 (source = feat via argument) ----
    k_gather<0><<<agrid, 256>>>(feat, 0, nullptr, nullptr);
    k_gemm128<<<ggrid, 256, smemGemm>>>(W1, 0);

    // ---- layer 2 (source = g_h bound in device code; BN1+ReLU fused) ----
    k_gather<1><<<agrid, 256>>>(nullptr, 0, gamma1, beta1);
    k_gemm128<<<ggrid, 256, smemGemm>>>(W2, 1);

    // ---- layer 3 (source = g_h bound in device code; BN2+ReLU fused) ----
    k_gather<1><<<agrid, 256>>>(nullptr, 1, gamma2, beta2);
    k_gemm_out<<<ggrid, 256, smemOut>>>(W3, b3, out);
}

// round 6
// speedup vs baseline: 1.8817x; 1.1066x over previous
#include <cuda_runtime.h>
#include <cuda_fp16.h>
#include <cstdint>

#define NN   100000
#define CC   128
#define EMAX 1600000
#define NB   ((NN + 255) / 256)        // 391 scan blocks

// ---------------- scratch (static device globals) --------------------------
__device__ __align__(16) float  g_agg[(size_t)NN * CC];  // 51.2 MB fp32 agg
__device__ __align__(16) __half g_hx[(size_t)NN * CC];   // 25.6 MB half features
__device__ int   g_cnt[NN];
__device__ int   g_rowstart[NN];
__device__ int   g_cursor[NN];
__device__ int   g_bsum[NB];
__device__ int   g_boff[NB];
__device__ int   g_psrc[EMAX];
__device__ float g_pw[EMAX];
__device__ double g_sum[2][CC];
__device__ double g_sumsq[2][CC];

// ---------------- CSR build + feat conversion ------------------------------
__global__ void __launch_bounds__(256) k_init()
{
    int i = blockIdx.x * 256 + threadIdx.x;
    if (i < NN) g_cnt[i] = 0;
    if (blockIdx.x == 0 && threadIdx.x < CC) {
        g_sum[0][threadIdx.x] = 0.0;  g_sumsq[0][threadIdx.x] = 0.0;
        g_sum[1][threadIdx.x] = 0.0;  g_sumsq[1][threadIdx.x] = 0.0;
    }
}

__global__ void __launch_bounds__(256) k_cvt(const float* __restrict__ feat)
{
    size_t i = (size_t)blockIdx.x * 256 + threadIdx.x;   // float4 index
    if (i < (size_t)NN * (CC / 4)) {
        float4 v = ((const float4*)feat)[i];
        __half2 h0 = __floats2half2_rn(v.x, v.y);
        __half2 h1 = __floats2half2_rn(v.z, v.w);
        uint2 p;
        p.x = *(unsigned*)&h0;
        p.y = *(unsigned*)&h1;
        ((uint2*)g_hx)[i] = p;
    }
}

__global__ void __launch_bounds__(256) k_hist(const int* __restrict__ dst, int E)
{
    int e = blockIdx.x * 256 + threadIdx.x;
    if (e < E) atomicAdd(&g_cnt[dst[e]], 1);
}

__global__ void __launch_bounds__(256) k_scan1()
{
    __shared__ int sm[256];
    int tid = threadIdx.x;
    int i = blockIdx.x * 256 + tid;
    int c = (i < NN) ? g_cnt[i] : 0;
    sm[tid] = c;
    __syncthreads();
    #pragma unroll
    for (int off = 1; off < 256; off <<= 1) {
        int v = (tid >= off) ? sm[tid - off] : 0;
        __syncthreads();
        sm[tid] += v;
        __syncthreads();
    }
    if (i < NN) g_rowstart[i] = sm[tid] - c;
    if (tid == 255) g_bsum[blockIdx.x] = sm[255];
}

__global__ void __launch_bounds__(512) k_scan2()
{
    __shared__ int sm[512];
    int tid = threadIdx.x;
    int v = (tid < NB) ? g_bsum[tid] : 0;
    sm[tid] = v;
    __syncthreads();
    #pragma unroll
    for (int off = 1; off < 512; off <<= 1) {
        int u = (tid >= off) ? sm[tid - off] : 0;
        __syncthreads();
        sm[tid] += u;
        __syncthreads();
    }
    if (tid < NB) g_boff[tid] = sm[tid] - v;
}

__global__ void __launch_bounds__(256) k_scan3()
{
    int i = blockIdx.x * 256 + threadIdx.x;
    if (i < NN) {
        int r = g_rowstart[i] + g_boff[blockIdx.x];
        g_rowstart[i] = r;
        g_cursor[i]   = r;
    }
}

__global__ void __launch_bounds__(256) k_fill(const int* __restrict__ src,
                                              const int* __restrict__ dst,
                                              const float* __restrict__ ew,
                                              int E)
{
    int e = blockIdx.x * 256 + threadIdx.x;
    if (e < E) {
        int slot = atomicAdd(&g_cursor[dst[e]], 1);
        g_psrc[slot] = src[e];
        g_pw[slot]   = ew[e];
    }
}

// ---------------- gather aggregation: warp per node, half source rows ------
// Source rows always come from the device symbol g_hx (half). AFF=1 applies
// BN affine + ReLU (coeffs from g_sum[sel]/g_sumsq[sel]) to each gathered row.
template<int AFF>
__global__ void __launch_bounds__(256) k_gather(int sel,
                                                const float* __restrict__ gamma,
                                                const float* __restrict__ beta)
{
    __shared__ float s_sc[CC], s_sh[CC];
    const int tid  = threadIdx.x;
    const int lane = tid & 31;

    if (AFF) {
        if (tid < CC) {
            double mean = g_sum[sel][tid]   * (1.0 / NN);
            double var  = g_sumsq[sel][tid] * (1.0 / NN) - mean * mean;
            float sc = gamma[tid] * rsqrtf((float)var + 1e-5f);
            s_sc[tid] = sc;
            s_sh[tid] = beta[tid] - (float)mean * sc;
        }
        __syncthreads();
    }

    int v = blockIdx.x * 8 + (tid >> 5);
    if (v >= NN) return;

    float4 sc4, sh4;
    if (AFF) {
        sc4 = *(const float4*)(s_sc + lane * 4);
        sh4 = *(const float4*)(s_sh + lane * 4);
    }

    const int start = g_rowstart[v];
    const int deg   = g_cnt[v];
    float4 acc = make_float4(0.f, 0.f, 0.f, 0.f);
    const __half* __restrict__ x = g_hx;

    for (int j = 0; j < deg; j++) {
        int   s0 = g_psrc[start + j];
        float w0 = g_pw[start + j];
        uint2 raw = *(const uint2*)(x + (size_t)s0 * CC + lane * 4);
        float2 f0 = __half22float2(*(__half2*)&raw.x);
        float2 f1 = __half22float2(*(__half2*)&raw.y);
        if (AFF) {
            f0.x = fmaxf(fmaf(f0.x, sc4.x, sh4.x), 0.f);
            f0.y = fmaxf(fmaf(f0.y, sc4.y, sh4.y), 0.f);
            f1.x = fmaxf(fmaf(f1.x, sc4.z, sh4.z), 0.f);
            f1.y = fmaxf(fmaf(f1.y, sc4.w, sh4.w), 0.f);
        }
        acc.x = fmaf(w0, f0.x, acc.x);
        acc.y = fmaf(w0, f0.y, acc.y);
        acc.z = fmaf(w0, f1.x, acc.z);
        acc.w = fmaf(w0, f1.y, acc.w);
    }
    *(float4*)(g_agg + (size_t)v * CC + lane * 4) = acc;
}

// ---------------- 128x128 GEMM (h = agg @ W) with fused BN stats -----------
// Writes h as HALF into g_hx; stats accumulated from fp32 pre-rounding values.
#define SMEM_GEMM_FLOATS (16384 + 128 * 132 + 256)
__global__ void __launch_bounds__(256) k_gemm128(const float* __restrict__ Wg,
                                                 int sel)
{
    extern __shared__ float sm[];
    float* Ws   = sm;               // 128*128
    float* As   = sm + 16384;       // 128 * 132 (padded)
    float* csum = As + 128 * 132;   // 128
    float* csq  = csum + 128;       // 128

    const int tid = threadIdx.x;
    const int tx  = tid & 15;
    const int ty  = tid >> 4;
    const int rowBase = blockIdx.x * 128;

    {
        const float4* W4  = (const float4*)Wg;
        float4*       Ws4 = (float4*)Ws;
        #pragma unroll
        for (int i = 0; i < 16; i++) Ws4[i * 256 + tid] = W4[i * 256 + tid];
    }
    #pragma unroll
    for (int i = 0; i < 16; i++) {
        int fl  = i * 256 + tid;
        int row = fl >> 5;
        int k4  = fl & 31;
        int grow = rowBase + row;
        float4 v = make_float4(0.f, 0.f, 0.f, 0.f);
        if (grow < NN) v = ((const float4*)g_agg)[(size_t)grow * 32 + k4];
        *(float4*)(As + row * 132 + k4 * 4) = v;
    }
    if (tid < 128) { csum[tid] = 0.f; csq[tid] = 0.f; }
    __syncthreads();

    unsigned long long acc[8][4];
    #pragma unroll
    for (int r = 0; r < 8; r++)
        #pragma unroll
        for (int c = 0; c < 4; c++) acc[r][c] = 0ull;

    const int    colBase = tx * 8;
    const float* AsR     = As + (ty * 8) * 132;

    #pragma unroll 4
    for (int k = 0; k < 128; k++) {
        const ulonglong2* wp = (const ulonglong2*)(Ws + k * 128 + colBase);
        ulonglong2 p0 = wp[0];
        ulonglong2 p1 = wp[1];
        unsigned long long bb0 = p0.x, bb1 = p0.y, bb2 = p1.x, bb3 = p1.y;
        #pragma unroll
        for (int r = 0; r < 8; r++) {
            float a = AsR[r * 132 + k];
            unsigned long long aa;
            asm("mov.b64 %0, {%1, %1};" : "=l"(aa) : "f"(a));
            asm("fma.rn.f32x2 %0, %1, %2, %0;" : "+l"(acc[r][0]) : "l"(aa), "l"(bb0));
            asm("fma.rn.f32x2 %0, %1, %2, %0;" : "+l"(acc[r][1]) : "l"(aa), "l"(bb1));
            asm("fma.rn.f32x2 %0, %1, %2, %0;" : "+l"(acc[r][2]) : "l"(aa), "l"(bb2));
            asm("fma.rn.f32x2 %0, %1, %2, %0;" : "+l"(acc[r][3]) : "l"(aa), "l"(bb3));
        }
    }

    float psum[8], psq[8];
    #pragma unroll
    for (int jj = 0; jj < 8; jj++) { psum[jj] = 0.f; psq[jj] = 0.f; }

    #pragma unroll
    for (int r = 0; r < 8; r++) {
        int grow = rowBase + ty * 8 + r;
        float v[8];
        #pragma unroll
        for (int c = 0; c < 4; c++)
            asm("mov.b64 {%0, %1}, %2;"
                : "=f"(v[c * 2]), "=f"(v[c * 2 + 1]) : "l"(acc[r][c]));
        if (grow < NN) {
            __half2 h0 = __floats2half2_rn(v[0], v[1]);
            __half2 h1 = __floats2half2_rn(v[2], v[3]);
            __half2 h2 = __floats2half2_rn(v[4], v[5]);
            __half2 h3 = __floats2half2_rn(v[6], v[7]);
            uint4 p;
            p.x = *(unsigned*)&h0;  p.y = *(unsigned*)&h1;
            p.z = *(unsigned*)&h2;  p.w = *(unsigned*)&h3;
            *(uint4*)(g_hx + (size_t)grow * CC + colBase) = p;
            #pragma unroll
            for (int jj = 0; jj < 8; jj++) { psum[jj] += v[jj]; psq[jj] += v[jj] * v[jj]; }
        }
    }
    #pragma unroll
    for (int jj = 0; jj < 8; jj++) {
        atomicAdd(&csum[colBase + jj], psum[jj]);
        atomicAdd(&csq[colBase + jj],  psq[jj]);
    }
    __syncthreads();
    if (tid < 128) {
        atomicAdd(&g_sum[sel][tid],   (double)csum[tid]);
        atomicAdd(&g_sumsq[sel][tid], (double)csq[tid]);
    }
}

// ---------------- final GEMM 128 -> 40 with bias, writes d_out -------------
#define SMEM_OUT_FLOATS (5120 + 128 * 132)
__global__ void __launch_bounds__(256) k_gemm_out(const float* __restrict__ W3,
                                                  const float* __restrict__ b3,
                                                  float* __restrict__ out)
{
    extern __shared__ float sm[];
    float* Ws = sm;            // 128*40
    float* As = sm + 5120;     // 128*132

    const int tid = threadIdx.x;
    const int rowBase = blockIdx.x * 128;

    for (int i = tid; i < 5120; i += 256) Ws[i] = W3[i];
    #pragma unroll
    for (int i = 0; i < 16; i++) {
        int fl  = i * 256 + tid;
        int row = fl >> 5;
        int k4  = fl & 31;
        int grow = rowBase + row;
        float4 v = make_float4(0.f, 0.f, 0.f, 0.f);
        if (grow < NN) v = ((const float4*)g_agg)[(size_t)grow * 32 + k4];
        *(float4*)(As + row * 132 + k4 * 4) = v;
    }
    __syncthreads();

    const int cg = tid & 7;
    const int rg = tid >> 3;
    float acc[4][5];
    #pragma unroll
    for (int r = 0; r < 4; r++)
        #pragma unroll
        for (int j = 0; j < 5; j++) acc[r][j] = 0.f;

    #pragma unroll 2
    for (int k = 0; k < 128; k++) {
        float b[5];
        #pragma unroll
        for (int j = 0; j < 5; j++) b[j] = Ws[k * 40 + cg * 5 + j];
        #pragma unroll
        for (int r = 0; r < 4; r++) {
            float a = As[(rg * 4 + r) * 132 + k];
            #pragma unroll
            for (int j = 0; j < 5; j++) acc[r][j] = fmaf(a, b[j], acc[r][j]);
        }
    }
    #pragma unroll
    for (int r = 0; r < 4; r++) {
        int grow = rowBase + rg * 4 + r;
        if (grow < NN) {
            #pragma unroll
            for (int j = 0; j < 5; j++)
                out[(size_t)grow * 40 + cg * 5 + j] = acc[r][j] + b3[cg * 5 + j];
        }
    }
}

// ---------------- launch ---------------------------------------------------
extern "C" void kernel_launch(void* const* d_in, const int* in_sizes, int n_in,
                              void* d_out, int out_size)
{
    const float* feat   = (const float*)d_in[0];
    const int*   src    = (const int*)  d_in[1];
    const int*   dst    = (const int*)  d_in[2];
    const float* ew     = (const float*)d_in[3];
    const float* W1     = (const float*)d_in[4];
    const float* W2     = (const float*)d_in[5];
    const float* W3     = (const float*)d_in[6];
    const float* b3     = (const float*)d_in[7];
    const float* gamma1 = (const float*)d_in[8];
    const float* beta1  = (const float*)d_in[9];
    const float* gamma2 = (const float*)d_in[10];
    const float* beta2  = (const float*)d_in[11];
    float* out = (float*)d_out;
    const int E = in_sizes[1];

    const int smemGemm = SMEM_GEMM_FLOATS * 4;
    const int smemOut  = SMEM_OUT_FLOATS  * 4;
    cudaFuncSetAttribute(k_gemm128,  cudaFuncAttributeMaxDynamicSharedMemorySize, smemGemm);
    cudaFuncSetAttribute(k_gemm_out, cudaFuncAttributeMaxDynamicSharedMemorySize, smemOut);

    const int egrid = (E + 255) / 256;
    const int ggrid = (NN + 127) / 128;
    const int agrid = (NN + 7) / 8;
    const int cgrid = (NN * (CC / 4) + 255) / 256;

    // ---- build CSR + convert feat to half (shared by all 3 layers) ----
    k_init <<<NB, 256>>>();
    k_cvt  <<<cgrid, 256>>>(feat);
    k_hist <<<egrid, 256>>>(dst, E);
    k_scan1<<<NB, 256>>>();
    k_scan2<<<1, 512>>>();
    k_scan3<<<NB, 256>>>();
    k_fill <<<egrid, 256>>>(src, dst, ew, E);

    // ---- layer 1 (gather from half feat) ----
    k_gather<0><<<agrid, 256>>>(0, nullptr, nullptr);
    k_gemm128<<<ggrid, 256, smemGemm>>>(W1, 0);

    // ---- layer 2 (gather from half h; BN1+ReLU fused) ----
    k_gather<1><<<agrid, 256>>>(0, gamma1, beta1);
    k_gemm128<<<ggrid, 256, smemGemm>>>(W2, 1);

    // ---- layer 3 (gather from half h; BN2+ReLU fused) ----
    k_gather<1><<<agrid, 256>>>(1, gamma2, beta2);
    k_gemm_out<<<ggrid, 256, smemOut>>>(W3, b3, out);
}